// round 5
// baseline (speedup 1.0000x reference)
#include <cuda_runtime.h>
#include <cstdint>

#define Bb  8
#define Tt  2048
#define Cc  1024
#define HSd 64
#define Mrows (Bb*Tt)
#define NQT  32
#define MAXCH 4
#define PPITCH 40          // proj smem pitch  (mod 32 == 8 -> conflict-free frags)
#define APITCH 72          // attn smem pitch  (mod 32 == 8)

// Projected q/k/v (tf32-rounded fp32 bits)
__device__ float g_q[Mrows*HSd];
__device__ float g_k[Mrows*HSd];
__device__ float g_v[Mrows*HSd];
// W: transposed [h][k], k-permuted, tf32-rounded (prep kernel)
__device__ float g_wt[3*Cc*HSd];
// Split-KV partials
__device__ float g_pO[Bb*NQT*MAXCH*64*64];
__device__ float g_pm[Bb*NQT*MAXCH*64];
__device__ float g_pl[Bb*NQT*MAXCH*64];

__device__ __forceinline__ uint32_t f2tf(float f) {
    uint32_t u;
    asm("cvt.rna.tf32.f32 %0, %1;" : "=r"(u) : "f"(f));
    return u;
}
__device__ __forceinline__ float tfv(float f) { return __uint_as_float(f2tf(f)); }
__device__ __forceinline__ float ex2(float x) {
    float r;
    asm("ex2.approx.ftz.f32 %0, %1;" : "=f"(r) : "f"(x));
    return r;
}
__device__ __forceinline__ void mma8(float* c, const uint32_t* a, uint32_t b0, uint32_t b1) {
    asm volatile(
        "mma.sync.aligned.m16n8k8.row.col.f32.tf32.tf32.f32 "
        "{%0,%1,%2,%3},{%4,%5,%6,%7},{%8,%9},{%0,%1,%2,%3};"
        : "+f"(c[0]), "+f"(c[1]), "+f"(c[2]), "+f"(c[3])
        : "r"(a[0]), "r"(a[1]), "r"(a[2]), "r"(a[3]), "r"(b0), "r"(b1));
}
__device__ __forceinline__ void cp16(uint32_t dst, const void* src) {
    asm volatile("cp.async.ca.shared.global [%0], [%1], 16;" :: "r"(dst), "l"(src));
}
#define CP_COMMIT() asm volatile("cp.async.commit_group;")
#define CP_WAIT0()  asm volatile("cp.async.wait_group 0;")

// ---------------------------------------------------------------------------
// Prep: W[k][h] -> g_wt[m][h][kperm], tf32-rounded. Tiny (3 x 64K elements).
// ---------------------------------------------------------------------------
__global__ __launch_bounds__(256)
void prep_w(const float* __restrict__ Wq, const float* __restrict__ Wk,
            const float* __restrict__ Wv)
{
    const int m = blockIdx.y;
    const float* W = (m == 0) ? Wq : ((m == 1) ? Wk : Wv);
    float* outp = g_wt + (size_t)m * Cc * HSd;
    const int h0 = blockIdx.x * 8;
    for (int i = threadIdx.x; i < 8 * Cc; i += 256) {
        int h = h0 + (i & 7);
        int k = i >> 3;
        int kp = (k & ~7) + 2 * (k & 3) + ((k >> 2) & 1);
        outp[(size_t)h * Cc + kp] = tfv(W[(size_t)k * HSd + h]);
    }
}

// ---------------------------------------------------------------------------
// Projection. CTA: 128 thr (4 warps), 128 rows x 64 cols, K-chunks of 32.
// Each warp: 2 m16 tiles (B fragments amortized). W via cp.async (pre-done).
// All fragment LDS are LDS.64, conflict-free (pitch 40, k-permuted).
// ---------------------------------------------------------------------------
__global__ __launch_bounds__(128, 3)
void proj_kernel(const float* __restrict__ qv, const float* __restrict__ kv,
                 const float* __restrict__ vv)
{
    extern __shared__ float sm[];
    float* As0 = sm;
    float* As1 = sm + 128*PPITCH;
    float* Ws0 = sm + 2*128*PPITCH;
    float* Ws1 = sm + 2*128*PPITCH + 64*PPITCH;

    const int m = blockIdx.y;
    const float* in  = (m == 0) ? qv : ((m == 1) ? kv : vv);
    float*       out = (m == 0) ? g_q : ((m == 1) ? g_k : g_v);
    const float* wt  = g_wt + (size_t)m * Cc * HSd;

    const int tid  = threadIdx.x;
    const int wid  = tid >> 5;
    const int lane = tid & 31;
    const int g    = lane >> 2;
    const int tig  = lane & 3;
    const int row0 = blockIdx.x * 128;
    const int m0w  = wid * 32;

    float4 pa[8];
    const int sR[4]  = { (tid      ) >> 2, (tid + 128) >> 2,
                         (tid + 256) >> 2, (tid + 384) >> 2 };
    const int sC[4]  = { (tid & 3) * 8, (tid & 3) * 8, (tid & 3) * 8, (tid & 3) * 8 };
    const int wh  = tid >> 1;
    const int wjb = (tid & 1) * 4;

#define LDA(k0)                                                               \
    { _Pragma("unroll") for (int i = 0; i < 4; i++) {                         \
        const float* p = in + (size_t)(row0 + sR[i])*Cc + (k0) + sC[i];       \
        pa[2*i]   = *(const float4*)p;                                        \
        pa[2*i+1] = *(const float4*)(p + 4); } }

#define STA(buf)                                                              \
    { _Pragma("unroll") for (int i = 0; i < 4; i++) {                         \
        float4 a = pa[2*i], b = pa[2*i+1];                                    \
        float4 v0 = make_float4(tfv(a.x), tfv(b.x), tfv(a.y), tfv(b.y));      \
        float4 v1 = make_float4(tfv(a.z), tfv(b.z), tfv(a.w), tfv(b.w));      \
        *(float4*)&(buf)[sR[i]*PPITCH + sC[i]]     = v0;                      \
        *(float4*)&(buf)[sR[i]*PPITCH + sC[i] + 4] = v1; } }

#define LDW(k0, buf)                                                          \
    { _Pragma("unroll") for (int i = 0; i < 4; i++) {                         \
        int j = wjb + i;                                                      \
        uint32_t dst = (uint32_t)__cvta_generic_to_shared(                    \
            &(buf)[wh*PPITCH + j*4]);                                         \
        cp16(dst, wt + (size_t)wh*Cc + (k0) + j*4); } }

    float acc[2][8][4];
#pragma unroll
    for (int mi = 0; mi < 2; mi++)
#pragma unroll
        for (int n = 0; n < 8; n++)
#pragma unroll
            for (int j = 0; j < 4; j++) acc[mi][n][j] = 0.f;

    LDA(0); STA(As0); LDW(0, Ws0); CP_COMMIT();

    for (int c = 0; c < 32; c++) {
        const int cur = c & 1;
        float* Ab = cur ? As1 : As0;
        float* Wb = cur ? Ws0 : Ws1;   // note: Wb here is the *other* buffer
        float* Ac = cur ? As0 : As1;   // unused names fixed below
        (void)Ab; (void)Wb; (void)Ac;
        float* Acur = cur ? As1 : As0;
        float* Wcur = cur ? Ws1 : Ws0;
        float* Anxt = cur ? As0 : As1;
        float* Wnxt = cur ? Ws0 : Ws1;

        CP_WAIT0();
        __syncthreads();
        if (c < 31) { LDW(32*(c+1), Wnxt); CP_COMMIT(); LDA(32*(c+1)); }

#pragma unroll
        for (int ks = 0; ks < 4; ks++) {
            float2 a0 = *(const float2*)&Acur[(m0w + g     )*PPITCH + 8*ks + 2*tig];
            float2 a1 = *(const float2*)&Acur[(m0w + g +  8)*PPITCH + 8*ks + 2*tig];
            float2 a2 = *(const float2*)&Acur[(m0w + g + 16)*PPITCH + 8*ks + 2*tig];
            float2 a3 = *(const float2*)&Acur[(m0w + g + 24)*PPITCH + 8*ks + 2*tig];
            uint32_t af0[4] = { __float_as_uint(a0.x), __float_as_uint(a1.x),
                                __float_as_uint(a0.y), __float_as_uint(a1.y) };
            uint32_t af1[4] = { __float_as_uint(a2.x), __float_as_uint(a3.x),
                                __float_as_uint(a2.y), __float_as_uint(a3.y) };
#pragma unroll
            for (int n = 0; n < 8; n++) {
                float2 bv = *(const float2*)&Wcur[(8*n + g)*PPITCH + 8*ks + 2*tig];
                uint32_t b0 = __float_as_uint(bv.x), b1 = __float_as_uint(bv.y);
                mma8(acc[0][n], af0, b0, b1);
                mma8(acc[1][n], af1, b0, b1);
            }
        }
        if (c < 31) STA(Anxt);
    }

#pragma unroll
    for (int mi = 0; mi < 2; mi++) {
        const int rb = row0 + m0w + mi*16;
#pragma unroll
        for (int n = 0; n < 8; n++) {
            *(float2*)(out + (size_t)(rb + g    )*HSd + 8*n + 2*tig) =
                make_float2(tfv(acc[mi][n][0]), tfv(acc[mi][n][1]));
            *(float2*)(out + (size_t)(rb + g + 8)*HSd + 8*n + 2*tig) =
                make_float2(tfv(acc[mi][n][2]), tfv(acc[mi][n][3]));
        }
    }
#undef LDA
#undef STA
#undef LDW
}

// ---------------------------------------------------------------------------
// Split-KV flash attention. Grid 640, 128 thr (4 warps), 64-row Q tile.
// K stored [kv][h_perm] (pitch 72), V transposed [h][kv_perm], P in KP rows.
// All fragment loads are LDS.64, conflict-free by pitch/permute construction.
// ---------------------------------------------------------------------------
__global__ __launch_bounds__(128, 4)
void attn_kernel(const int* __restrict__ mask, float* __restrict__ out)
{
    __shared__ float KP[64*APITCH];
    __shared__ float Vs[64*APITCH];
    __shared__ int   msk[64];

    const int i = blockIdx.x;
    const int b = i & 7;
    const int r = i >> 3;
    int qb, chunk;
    if (r < 32)      { qb = 24 + (r >> 2);       chunk = r & 3; }
    else if (r < 56) { int t = r - 32; qb = 16 + t/3; chunk = t - 3*(t/3); }
    else if (r < 72) { int t = r - 56; qb = 8 + (t >> 1); chunk = t & 1; }
    else             { qb = r - 72;              chunk = 0; }
    const int nch   = (qb + 8) >> 3;
    const int kb_lo = chunk * 8;
    const int kb_hi = min(kb_lo + 8, qb + 1);

    const int q0   = qb * 64;
    const int tid  = threadIdx.x;
    const int wid  = tid >> 5;
    const int lane = tid & 31;
    const int g    = lane >> 2;
    const int tig  = lane & 3;
    const int m0w  = wid * 16;

    // Q fragments from logical-layout g_q (tf32 bits already)
    uint32_t qf[8][4];
    const float* qbase = g_q + (size_t)(b*Tt + q0 + m0w)*HSd;
#pragma unroll
    for (int k = 0; k < 8; k++) {
        qf[k][0] = __float_as_uint(qbase[(g    )*HSd + 8*k + tig    ]);
        qf[k][1] = __float_as_uint(qbase[(g + 8)*HSd + 8*k + tig    ]);
        qf[k][2] = __float_as_uint(qbase[(g    )*HSd + 8*k + tig + 4]);
        qf[k][3] = __float_as_uint(qbase[(g + 8)*HSd + 8*k + tig + 4]);
    }

    float o[8][4];
#pragma unroll
    for (int n = 0; n < 8; n++)
#pragma unroll
        for (int j = 0; j < 4; j++) o[n][j] = 0.f;
    float mr0 = -1e30f, mr1 = -1e30f, lr0 = 0.f, lr1 = 0.f;

    const float scale2 = 0.125f * 1.4426950408889634f;
    const int row0g = q0 + m0w + g;
    const int row1g = row0g + 8;
    const int vrow  = tid >> 1;
    const int vh0   = (tid & 1) * 32;
    const int vpc   = (vrow & ~7) + 2*(vrow & 3) + ((vrow >> 2) & 1);
    const int pA    = (tig & 1)*4 + (tig >> 1);   // perm pos of col 2*tig
    const int pB    = pA + 2;                     // perm pos of col 2*tig+1

    for (int kb = kb_lo; kb < kb_hi; kb++) {
        const int k0 = kb * 64;
        __syncthreads();

        const float* kg = g_k + (size_t)(b*Tt + k0)*HSd;
        const float* vg = g_v + (size_t)(b*Tt + k0)*HSd;
        // K: [kv][h_perm]
#pragma unroll
        for (int ii = 0; ii < 4; ii++) {
            int s = tid + 128*ii;
            int rr = s >> 3, cg = (s & 7) * 8;
            const float* p = kg + rr*HSd + cg;
            float4 a = *(const float4*)p, bvv = *(const float4*)(p + 4);
            *(float4*)&KP[rr*APITCH + cg]     = make_float4(a.x, bvv.x, a.y, bvv.y);
            *(float4*)&KP[rr*APITCH + cg + 4] = make_float4(a.z, bvv.z, a.w, bvv.w);
        }
        // V transposed: [h][kv_perm]
#pragma unroll
        for (int j = 0; j < 8; j++) {
            float4 v = *(const float4*)(vg + vrow*HSd + vh0 + 4*j);
            Vs[(vh0 + 4*j + 0)*APITCH + vpc] = v.x;
            Vs[(vh0 + 4*j + 1)*APITCH + vpc] = v.y;
            Vs[(vh0 + 4*j + 2)*APITCH + vpc] = v.z;
            Vs[(vh0 + 4*j + 3)*APITCH + vpc] = v.w;
        }
        if (tid < 64) msk[tid] = mask[b*Tt + k0 + tid];
        __syncthreads();

        // ---- S = Q K^T ----
        float s[8][4];
#pragma unroll
        for (int n = 0; n < 8; n++)
#pragma unroll
            for (int j = 0; j < 4; j++) s[n][j] = 0.f;
#pragma unroll
        for (int k = 0; k < 8; k++) {
#pragma unroll
            for (int n = 0; n < 8; n++) {
                float2 bv = *(const float2*)&KP[(8*n + g)*APITCH + 8*k + 2*tig];
                mma8(s[n], qf[k], __float_as_uint(bv.x), __float_as_uint(bv.y));
            }
        }

        // ---- scale (log2) + causal/pad mask ----
        const bool diag = (kb == qb);
#pragma unroll
        for (int n = 0; n < 8; n++) {
            int cl = 8*n + 2*tig;
            int2 mm = *(const int2*)&msk[cl];
            int c0 = k0 + cl, c1 = c0 + 1;
            bool v00 = (mm.x != 0) && (!diag || c0 <= row0g);
            bool v01 = (mm.y != 0) && (!diag || c1 <= row0g);
            bool v10 = (mm.x != 0) && (!diag || c0 <= row1g);
            bool v11 = (mm.y != 0) && (!diag || c1 <= row1g);
            s[n][0] = v00 ? s[n][0]*scale2 : -1e30f;
            s[n][1] = v01 ? s[n][1]*scale2 : -1e30f;
            s[n][2] = v10 ? s[n][2]*scale2 : -1e30f;
            s[n][3] = v11 ? s[n][3]*scale2 : -1e30f;
        }

        // ---- online softmax, base-2 ----
        {
            float m0 = -1e30f, m1 = -1e30f;
#pragma unroll
            for (int n = 0; n < 8; n++) {
                m0 = fmaxf(m0, fmaxf(s[n][0], s[n][1]));
                m1 = fmaxf(m1, fmaxf(s[n][2], s[n][3]));
            }
#pragma unroll
            for (int off = 1; off < 4; off <<= 1) {
                m0 = fmaxf(m0, __shfl_xor_sync(0xffffffffu, m0, off));
                m1 = fmaxf(m1, __shfl_xor_sync(0xffffffffu, m1, off));
            }
            float mn0 = fmaxf(mr0, m0), mn1 = fmaxf(mr1, m1);
            float al0 = ex2(mr0 - mn0), al1 = ex2(mr1 - mn1);
            float ls0 = 0.f, ls1 = 0.f;
#pragma unroll
            for (int n = 0; n < 8; n++) {
                s[n][0] = ex2(s[n][0] - mn0);
                s[n][1] = ex2(s[n][1] - mn0);
                s[n][2] = ex2(s[n][2] - mn1);
                s[n][3] = ex2(s[n][3] - mn1);
                ls0 += s[n][0] + s[n][1];
                ls1 += s[n][2] + s[n][3];
            }
#pragma unroll
            for (int off = 1; off < 4; off <<= 1) {
                ls0 += __shfl_xor_sync(0xffffffffu, ls0, off);
                ls1 += __shfl_xor_sync(0xffffffffu, ls1, off);
            }
            lr0 = lr0*al0 + ls0;  mr0 = mn0;
            lr1 = lr1*al1 + ls1;  mr1 = mn1;
#pragma unroll
            for (int n = 0; n < 8; n++) {
                o[n][0] *= al0; o[n][1] *= al0;
                o[n][2] *= al1; o[n][3] *= al1;
            }
        }

        __syncthreads();   // K readers done before P overwrites KP
        // ---- P (tf32) into own rows, kv-permuted cols ----
#pragma unroll
        for (int n = 0; n < 8; n++) {
            KP[(m0w + g    )*APITCH + 8*n + pA] = tfv(s[n][0]);
            KP[(m0w + g    )*APITCH + 8*n + pB] = tfv(s[n][1]);
            KP[(m0w + g + 8)*APITCH + 8*n + pA] = tfv(s[n][2]);
            KP[(m0w + g + 8)*APITCH + 8*n + pB] = tfv(s[n][3]);
        }
        __syncwarp();

        // ---- O += P V ----
#pragma unroll
        for (int k = 0; k < 8; k++) {
            float2 a0 = *(const float2*)&KP[(m0w + g    )*APITCH + 8*k + 2*tig];
            float2 a1 = *(const float2*)&KP[(m0w + g + 8)*APITCH + 8*k + 2*tig];
            uint32_t af[4] = { __float_as_uint(a0.x), __float_as_uint(a1.x),
                               __float_as_uint(a0.y), __float_as_uint(a1.y) };
#pragma unroll
            for (int n = 0; n < 8; n++) {
                float2 bv = *(const float2*)&Vs[(8*n + g)*APITCH + 8*k + 2*tig];
                mma8(o[n], af, __float_as_uint(bv.x), __float_as_uint(bv.y));
            }
        }
    }

    // ---- epilogue ----
    if (nch == 1) {
        const float inv0 = 1.0f / lr0, inv1 = 1.0f / lr1;
        float* obase = out + (size_t)(b*Tt + q0 + m0w)*HSd;
#pragma unroll
        for (int n = 0; n < 8; n++) {
            *(float2*)(obase + (g    )*HSd + 8*n + 2*tig) =
                make_float2(o[n][0]*inv0, o[n][1]*inv0);
            *(float2*)(obase + (g + 8)*HSd + 8*n + 2*tig) =
                make_float2(o[n][2]*inv1, o[n][3]*inv1);
        }
    } else {
        const size_t idx = (size_t)((b*NQT + qb)*MAXCH + chunk);
        float* pO = g_pO + idx*4096;
#pragma unroll
        for (int n = 0; n < 8; n++) {
            *(float2*)&pO[(m0w + g    )*64 + 8*n + 2*tig] =
                make_float2(o[n][0], o[n][1]);
            *(float2*)&pO[(m0w + g + 8)*64 + 8*n + 2*tig] =
                make_float2(o[n][2], o[n][3]);
        }
        if (tig == 0) {
            g_pm[idx*64 + m0w + g    ] = mr0;
            g_pl[idx*64 + m0w + g    ] = lr0;
            g_pm[idx*64 + m0w + g + 8] = mr1;
            g_pl[idx*64 + m0w + g + 8] = lr1;
        }
    }
}

// ---------------------------------------------------------------------------
// Combine partials for qb >= 8. Grid (24, 8) x 128 thr.
// ---------------------------------------------------------------------------
__global__ __launch_bounds__(128)
void combine_kernel(float* __restrict__ out)
{
    const int qb  = 8 + blockIdx.x;
    const int b   = blockIdx.y;
    const int nch = (qb + 8) >> 3;
    const int t   = threadIdx.x;
    const int row = t >> 1;
    const int half = (t & 1) * 32;
    const int base = (b*NQT + qb)*MAXCH;

    float mg = -1e30f;
    for (int i = 0; i < nch; i++)
        mg = fmaxf(mg, g_pm[(base + i)*64 + row]);

    float l = 0.f;
    float4 acc[8];
#pragma unroll
    for (int j = 0; j < 8; j++) acc[j] = make_float4(0.f, 0.f, 0.f, 0.f);

    for (int i = 0; i < nch; i++) {
        float w = ex2(g_pm[(base + i)*64 + row] - mg);
        l += w * g_pl[(base + i)*64 + row];
        const float4* src = (const float4*)&g_pO[(size_t)(base + i)*4096 + row*64 + half];
#pragma unroll
        for (int j = 0; j < 8; j++) {
            float4 v = src[j];
            acc[j].x += w*v.x; acc[j].y += w*v.y;
            acc[j].z += w*v.z; acc[j].w += w*v.w;
        }
    }

    const float inv = 1.0f / l;
    float4* dst = (float4*)(out + (size_t)(b*Tt + qb*64 + row)*HSd + half);
#pragma unroll
    for (int j = 0; j < 8; j++)
        dst[j] = make_float4(acc[j].x*inv, acc[j].y*inv, acc[j].z*inv, acc[j].w*inv);
}

// ---------------------------------------------------------------------------
extern "C" void kernel_launch(void* const* d_in, const int* in_sizes, int n_in,
                              void* d_out, int out_size)
{
    const float* q_vec = (const float*)d_in[0];
    const float* k_vec = (const float*)d_in[1];
    const float* v_vec = (const float*)d_in[2];
    const int*   mask  = (const int*)  d_in[3];
    const float* Wq    = (const float*)d_in[4];
    const float* Wk    = (const float*)d_in[5];
    const float* Wv    = (const float*)d_in[6];
    float* out = (float*)d_out;

    const int proj_smem = (2*128*PPITCH + 2*64*PPITCH) * 4;   // 61440 B
    cudaFuncSetAttribute(proj_kernel,
                         cudaFuncAttributeMaxDynamicSharedMemorySize, proj_smem);

    prep_w<<<dim3(8, 3), 256>>>(Wq, Wk, Wv);
    proj_kernel<<<dim3(Mrows/128, 3), 128, proj_smem>>>(q_vec, k_vec, v_vec);
    attn_kernel<<<640, 128>>>(mask, out);
    combine_kernel<<<dim3(24, 8), 128>>>(out);
}

// round 6
// speedup vs baseline: 1.1774x; 1.1774x over previous
#include <cuda_runtime.h>
#include <cstdint>

#define Bb  8
#define Tt  2048
#define Cc  1024
#define HSd 64
#define Mrows (Bb*Tt)
#define NQT  32
#define MAXCH 4
#define PPITCH 40          // proj A pitch (mod 32 == 8 -> LDS.64 frags conflict-free)

// Projected q/k/v (tf32-rounded fp32 bits)
__device__ float g_q[Mrows*HSd];
__device__ float g_k[Mrows*HSd];
__device__ float g_v[Mrows*HSd];
// W, tf32-pre-rounded, layout unchanged [k][h]
__device__ float g_wt[3*Cc*HSd];
// Split-KV partials
__device__ float g_pO[Bb*NQT*MAXCH*64*64];
__device__ float g_pm[Bb*NQT*MAXCH*64];
__device__ float g_pl[Bb*NQT*MAXCH*64];

__device__ __forceinline__ uint32_t f2tf(float f) {
    uint32_t u;
    asm("cvt.rna.tf32.f32 %0, %1;" : "=r"(u) : "f"(f));
    return u;
}
__device__ __forceinline__ float tfv(float f) { return __uint_as_float(f2tf(f)); }
__device__ __forceinline__ float ex2(float x) {
    float r;
    asm("ex2.approx.ftz.f32 %0, %1;" : "=f"(r) : "f"(x));
    return r;
}
__device__ __forceinline__ void mma8(float* c, const uint32_t* a, uint32_t b0, uint32_t b1) {
    asm volatile(
        "mma.sync.aligned.m16n8k8.row.col.f32.tf32.tf32.f32 "
        "{%0,%1,%2,%3},{%4,%5,%6,%7},{%8,%9},{%0,%1,%2,%3};"
        : "+f"(c[0]), "+f"(c[1]), "+f"(c[2]), "+f"(c[3])
        : "r"(a[0]), "r"(a[1]), "r"(a[2]), "r"(a[3]), "r"(b0), "r"(b1));
}

// ---------------------------------------------------------------------------
// Prep: tf32-round W in place-layout [k][h] -> g_wt. 3 x 64K elems, trivial.
// ---------------------------------------------------------------------------
__global__ __launch_bounds__(256)
void prep_w(const float* __restrict__ Wq, const float* __restrict__ Wk,
            const float* __restrict__ Wv)
{
    const int m = blockIdx.y;
    const float* W = (m == 0) ? Wq : ((m == 1) ? Wk : Wv);
    float* outp = g_wt + (size_t)m * Cc * HSd;
    const int i = (blockIdx.x * 256 + threadIdx.x) * 4;
    float4 v = *(const float4*)(W + i);
    *(float4*)(outp + i) = make_float4(tfv(v.x), tfv(v.y), tfv(v.z), tfv(v.w));
}

// ---------------------------------------------------------------------------
// Projection. CTA: 128 thr (4 warps), 128 rows x 64 cols, K-chunks of 32.
// Each warp: 2 m16 tiles (B fragments amortized over 2 mmas).
// A: k-permuted pairs (cols j, j+4 adjacent) -> LDS.64 fragment loads,
//    pitch 40, conflict-free. W: [k][h] pitch 72, pre-rounded, scalar B LDS.
// Double-buffered LDG->reg->STS, one barrier per chunk.
// ---------------------------------------------------------------------------
__global__ __launch_bounds__(128, 3)
void proj_kernel(const float* __restrict__ qv, const float* __restrict__ kv,
                 const float* __restrict__ vv)
{
    extern __shared__ float sm[];
    float* As0 = sm;                       // 128*40
    float* As1 = sm + 128*PPITCH;
    float* Ws0 = sm + 2*128*PPITCH;        // 32*72
    float* Ws1 = sm + 2*128*PPITCH + 32*72;

    const int m = blockIdx.y;
    const float* in  = (m == 0) ? qv : ((m == 1) ? kv : vv);
    float*       out = (m == 0) ? g_q : ((m == 1) ? g_k : g_v);
    const float* wt  = g_wt + (size_t)m * Cc * HSd;

    const int tid  = threadIdx.x;
    const int wid  = tid >> 5;
    const int lane = tid & 31;
    const int g    = lane >> 2;
    const int tig  = lane & 3;
    const int row0 = blockIdx.x * 128;
    const int m0w  = wid * 32;

    const int aR = tid >> 2;          // +32*i
    const int aC = (tid & 3) * 8;     // logical k-group base in chunk
    const int wR = tid >> 2;          // W rows 0..31
    const int wC = (tid & 3) * 16;    // W cols 0..63, 16 each

    float4 pa[8];                     // A stage: 4 rows x 8 floats
    float4 pw[4];                     // W stage: 1 row x 16 floats

#define LDA(k0)                                                               \
    { _Pragma("unroll") for (int i = 0; i < 4; i++) {                         \
        const float* p = in + (size_t)(row0 + aR + 32*i)*Cc + (k0) + aC;      \
        pa[2*i]   = *(const float4*)p;                                        \
        pa[2*i+1] = *(const float4*)(p + 4); } }

#define LDWm(k0)                                                              \
    { const float* p = wt + (size_t)((k0) + wR)*HSd + wC;                     \
      _Pragma("unroll") for (int i = 0; i < 4; i++)                           \
          pw[i] = *(const float4*)(p + 4*i); }

#define STAB(buf)                                                             \
    { _Pragma("unroll") for (int i = 0; i < 4; i++) {                         \
        float4 a = pa[2*i], b = pa[2*i+1];                                    \
        *(float4*)&(buf)[(aR + 32*i)*PPITCH + aC] =                           \
            make_float4(tfv(a.x), tfv(b.x), tfv(a.y), tfv(b.y));              \
        *(float4*)&(buf)[(aR + 32*i)*PPITCH + aC + 4] =                       \
            make_float4(tfv(a.z), tfv(b.z), tfv(a.w), tfv(b.w)); } }

#define STWB(buf)                                                             \
    { _Pragma("unroll") for (int i = 0; i < 4; i++)                           \
        *(float4*)&(buf)[wR*72 + wC + 4*i] = pw[i]; }

    float acc[2][8][4];
#pragma unroll
    for (int mi = 0; mi < 2; mi++)
#pragma unroll
        for (int n = 0; n < 8; n++)
#pragma unroll
            for (int j = 0; j < 4; j++) acc[mi][n][j] = 0.f;

    LDA(0); LDWm(0);
    STAB(As0); STWB(Ws0);
    __syncthreads();

    for (int c = 0; c < 32; c++) {
        const int cur = c & 1;
        float* Acur = cur ? As1 : As0;
        float* Wcur = cur ? Ws1 : Ws0;
        float* Anxt = cur ? As0 : As1;
        float* Wnxt = cur ? Ws0 : Ws1;

        if (c < 31) { LDA(32*(c+1)); LDWm(32*(c+1)); }

#pragma unroll
        for (int ks = 0; ks < 4; ks++) {
            float2 a0 = *(const float2*)&Acur[(m0w + g     )*PPITCH + 8*ks + 2*tig];
            float2 a1 = *(const float2*)&Acur[(m0w + g +  8)*PPITCH + 8*ks + 2*tig];
            float2 a2 = *(const float2*)&Acur[(m0w + g + 16)*PPITCH + 8*ks + 2*tig];
            float2 a3 = *(const float2*)&Acur[(m0w + g + 24)*PPITCH + 8*ks + 2*tig];
            uint32_t af0[4] = { __float_as_uint(a0.x), __float_as_uint(a1.x),
                                __float_as_uint(a0.y), __float_as_uint(a1.y) };
            uint32_t af1[4] = { __float_as_uint(a2.x), __float_as_uint(a3.x),
                                __float_as_uint(a2.y), __float_as_uint(a3.y) };
#pragma unroll
            for (int n = 0; n < 8; n++) {
                uint32_t b0 = __float_as_uint(Wcur[(8*ks + tig    )*72 + 8*n + g]);
                uint32_t b1 = __float_as_uint(Wcur[(8*ks + tig + 4)*72 + 8*n + g]);
                mma8(acc[0][n], af0, b0, b1);
                mma8(acc[1][n], af1, b0, b1);
            }
        }
        if (c < 31) { STAB(Anxt); STWB(Wnxt); }
        __syncthreads();
    }

#pragma unroll
    for (int mi = 0; mi < 2; mi++) {
        const int rb = row0 + m0w + mi*16;
#pragma unroll
        for (int n = 0; n < 8; n++) {
            *(float2*)(out + (size_t)(rb + g    )*HSd + 8*n + 2*tig) =
                make_float2(tfv(acc[mi][n][0]), tfv(acc[mi][n][1]));
            *(float2*)(out + (size_t)(rb + g + 8)*HSd + 8*n + 2*tig) =
                make_float2(tfv(acc[mi][n][2]), tfv(acc[mi][n][3]));
        }
    }
#undef LDA
#undef LDWm
#undef STAB
#undef STWB
}

// ---------------------------------------------------------------------------
// Split-KV flash attention — EXACT round-4 version (known good).
// ---------------------------------------------------------------------------
__global__ __launch_bounds__(128, 4)
void attn_kernel(const int* __restrict__ mask, float* __restrict__ out)
{
    __shared__ float KP[64*68];
    __shared__ float Vs[64*72];
    __shared__ int   msk[64];

    const int i = blockIdx.x;
    const int b = i & 7;
    const int r = i >> 3;
    int qb, chunk;
    if (r < 32)      { qb = 24 + (r >> 2);       chunk = r & 3; }
    else if (r < 56) { int t = r - 32; qb = 16 + t/3; chunk = t - 3*(t/3); }
    else if (r < 72) { int t = r - 56; qb = 8 + (t >> 1); chunk = t & 1; }
    else             { qb = r - 72;              chunk = 0; }
    const int nch   = (qb + 8) >> 3;
    const int kb_lo = chunk * 8;
    const int kb_hi = min(kb_lo + 8, qb + 1);

    const int q0   = qb * 64;
    const int tid  = threadIdx.x;
    const int wid  = tid >> 5;
    const int lane = tid & 31;
    const int g    = lane >> 2;
    const int tig  = lane & 3;
    const int m0w  = wid * 16;

    uint32_t qf[8][4];
    const float* qbase = g_q + (size_t)(b*Tt + q0 + m0w)*HSd;
#pragma unroll
    for (int k = 0; k < 8; k++) {
        qf[k][0] = __float_as_uint(qbase[(g    )*HSd + 8*k + tig    ]);
        qf[k][1] = __float_as_uint(qbase[(g + 8)*HSd + 8*k + tig    ]);
        qf[k][2] = __float_as_uint(qbase[(g    )*HSd + 8*k + tig + 4]);
        qf[k][3] = __float_as_uint(qbase[(g + 8)*HSd + 8*k + tig + 4]);
    }

    float o[8][4];
#pragma unroll
    for (int n = 0; n < 8; n++)
#pragma unroll
        for (int j = 0; j < 4; j++) o[n][j] = 0.f;
    float mr0 = -1e30f, mr1 = -1e30f, lr0 = 0.f, lr1 = 0.f;

    const float scale2 = 0.125f * 1.4426950408889634f;
    const int row0g = q0 + m0w + g;
    const int row1g = row0g + 8;

    for (int kb = kb_lo; kb < kb_hi; kb++) {
        const int k0 = kb * 64;
        __syncthreads();

        const float* kg = g_k + (size_t)(b*Tt + k0)*HSd;
        const float* vg = g_v + (size_t)(b*Tt + k0)*HSd;
#pragma unroll
        for (int t = tid; t < 1024; t += 128) {
            int rr = t >> 4, c4 = (t & 15) << 2;
            *(float4*)&KP[rr*68 + c4] = *(const float4*)(kg + rr*HSd + c4);
            *(float4*)&Vs[rr*72 + c4] = *(const float4*)(vg + rr*HSd + c4);
        }
        if (tid < 64) msk[tid] = mask[b*Tt + k0 + tid];
        __syncthreads();

        float s[8][4];
#pragma unroll
        for (int n = 0; n < 8; n++)
#pragma unroll
            for (int j = 0; j < 4; j++) s[n][j] = 0.f;
#pragma unroll
        for (int k = 0; k < 8; k++) {
#pragma unroll
            for (int n = 0; n < 8; n++) {
                uint32_t b0 = __float_as_uint(KP[(8*n + g)*68 + 8*k + tig    ]);
                uint32_t b1 = __float_as_uint(KP[(8*n + g)*68 + 8*k + tig + 4]);
                mma8(s[n], qf[k], b0, b1);
            }
        }

        const bool diag = (kb == qb);
#pragma unroll
        for (int n = 0; n < 8; n++) {
            int cl = 8*n + 2*tig;
            int2 mm = *(const int2*)&msk[cl];
            int c0 = k0 + cl, c1 = c0 + 1;
            bool v00 = (mm.x != 0) && (!diag || c0 <= row0g);
            bool v01 = (mm.y != 0) && (!diag || c1 <= row0g);
            bool v10 = (mm.x != 0) && (!diag || c0 <= row1g);
            bool v11 = (mm.y != 0) && (!diag || c1 <= row1g);
            s[n][0] = v00 ? s[n][0]*scale2 : -1e30f;
            s[n][1] = v01 ? s[n][1]*scale2 : -1e30f;
            s[n][2] = v10 ? s[n][2]*scale2 : -1e30f;
            s[n][3] = v11 ? s[n][3]*scale2 : -1e30f;
        }

        {
            float m0 = -1e30f, m1 = -1e30f;
#pragma unroll
            for (int n = 0; n < 8; n++) {
                m0 = fmaxf(m0, fmaxf(s[n][0], s[n][1]));
                m1 = fmaxf(m1, fmaxf(s[n][2], s[n][3]));
            }
#pragma unroll
            for (int off = 1; off < 4; off <<= 1) {
                m0 = fmaxf(m0, __shfl_xor_sync(0xffffffffu, m0, off));
                m1 = fmaxf(m1, __shfl_xor_sync(0xffffffffu, m1, off));
            }
            float mn0 = fmaxf(mr0, m0), mn1 = fmaxf(mr1, m1);
            float al0 = ex2(mr0 - mn0), al1 = ex2(mr1 - mn1);
            float ls0 = 0.f, ls1 = 0.f;
#pragma unroll
            for (int n = 0; n < 8; n++) {
                s[n][0] = ex2(s[n][0] - mn0);
                s[n][1] = ex2(s[n][1] - mn0);
                s[n][2] = ex2(s[n][2] - mn1);
                s[n][3] = ex2(s[n][3] - mn1);
                ls0 += s[n][0] + s[n][1];
                ls1 += s[n][2] + s[n][3];
            }
#pragma unroll
            for (int off = 1; off < 4; off <<= 1) {
                ls0 += __shfl_xor_sync(0xffffffffu, ls0, off);
                ls1 += __shfl_xor_sync(0xffffffffu, ls1, off);
            }
            lr0 = lr0*al0 + ls0;  mr0 = mn0;
            lr1 = lr1*al1 + ls1;  mr1 = mn1;
#pragma unroll
            for (int n = 0; n < 8; n++) {
                o[n][0] *= al0; o[n][1] *= al0;
                o[n][2] *= al1; o[n][3] *= al1;
            }
        }

        __syncthreads();
#pragma unroll
        for (int n = 0; n < 8; n++) {
            float2 p0 = make_float2(tfv(s[n][0]), tfv(s[n][1]));
            float2 p1 = make_float2(tfv(s[n][2]), tfv(s[n][3]));
            *(float2*)&KP[(m0w + g    )*68 + 8*n + 2*tig] = p0;
            *(float2*)&KP[(m0w + g + 8)*68 + 8*n + 2*tig] = p1;
        }
        __syncwarp();

#pragma unroll
        for (int k = 0; k < 8; k++) {
            uint32_t af[4];
            af[0] = __float_as_uint(KP[(m0w + g    )*68 + 8*k + tig    ]);
            af[1] = __float_as_uint(KP[(m0w + g + 8)*68 + 8*k + tig    ]);
            af[2] = __float_as_uint(KP[(m0w + g    )*68 + 8*k + tig + 4]);
            af[3] = __float_as_uint(KP[(m0w + g + 8)*68 + 8*k + tig + 4]);
#pragma unroll
            for (int n = 0; n < 8; n++) {
                uint32_t b0 = __float_as_uint(Vs[(8*k + tig    )*72 + 8*n + g]);
                uint32_t b1 = __float_as_uint(Vs[(8*k + tig + 4)*72 + 8*n + g]);
                mma8(o[n], af, b0, b1);
            }
        }
    }

    if (nch == 1) {
        const float inv0 = 1.0f / lr0, inv1 = 1.0f / lr1;
        float* obase = out + (size_t)(b*Tt + q0 + m0w)*HSd;
#pragma unroll
        for (int n = 0; n < 8; n++) {
            *(float2*)(obase + (g    )*HSd + 8*n + 2*tig) =
                make_float2(o[n][0]*inv0, o[n][1]*inv0);
            *(float2*)(obase + (g + 8)*HSd + 8*n + 2*tig) =
                make_float2(o[n][2]*inv1, o[n][3]*inv1);
        }
    } else {
        const size_t idx = (size_t)((b*NQT + qb)*MAXCH + chunk);
        float* pO = g_pO + idx*4096;
#pragma unroll
        for (int n = 0; n < 8; n++) {
            *(float2*)&pO[(m0w + g    )*64 + 8*n + 2*tig] =
                make_float2(o[n][0], o[n][1]);
            *(float2*)&pO[(m0w + g + 8)*64 + 8*n + 2*tig] =
                make_float2(o[n][2], o[n][3]);
        }
        if (tig == 0) {
            g_pm[idx*64 + m0w + g    ] = mr0;
            g_pl[idx*64 + m0w + g    ] = lr0;
            g_pm[idx*64 + m0w + g + 8] = mr1;
            g_pl[idx*64 + m0w + g + 8] = lr1;
        }
    }
}

// ---------------------------------------------------------------------------
// Combine partials for qb >= 8. Grid (24, 8) x 256 thr (more MLP than r4).
// ---------------------------------------------------------------------------
__global__ __launch_bounds__(256)
void combine_kernel(float* __restrict__ out)
{
    const int qb  = 8 + blockIdx.x;
    const int b   = blockIdx.y;
    const int nch = (qb + 8) >> 3;
    const int t   = threadIdx.x;
    const int row = t >> 2;
    const int qtr = (t & 3) * 16;
    const int base = (b*NQT + qb)*MAXCH;

    float mg = -1e30f;
    for (int i = 0; i < nch; i++)
        mg = fmaxf(mg, g_pm[(base + i)*64 + row]);

    float l = 0.f;
    float4 acc[4];
#pragma unroll
    for (int j = 0; j < 4; j++) acc[j] = make_float4(0.f, 0.f, 0.f, 0.f);

    for (int i = 0; i < nch; i++) {
        float w = ex2(g_pm[(base + i)*64 + row] - mg);
        l += w * g_pl[(base + i)*64 + row];
        const float4* src = (const float4*)&g_pO[(size_t)(base + i)*4096 + row*64 + qtr];
#pragma unroll
        for (int j = 0; j < 4; j++) {
            float4 v = src[j];
            acc[j].x += w*v.x; acc[j].y += w*v.y;
            acc[j].z += w*v.z; acc[j].w += w*v.w;
        }
    }

    const float inv = 1.0f / l;
    float4* dst = (float4*)(out + (size_t)(b*Tt + qb*64 + row)*HSd + qtr);
#pragma unroll
    for (int j = 0; j < 4; j++)
        dst[j] = make_float4(acc[j].x*inv, acc[j].y*inv, acc[j].z*inv, acc[j].w*inv);
}

// ---------------------------------------------------------------------------
extern "C" void kernel_launch(void* const* d_in, const int* in_sizes, int n_in,
                              void* d_out, int out_size)
{
    const float* q_vec = (const float*)d_in[0];
    const float* k_vec = (const float*)d_in[1];
    const float* v_vec = (const float*)d_in[2];
    const int*   mask  = (const int*)  d_in[3];
    const float* Wq    = (const float*)d_in[4];
    const float* Wk    = (const float*)d_in[5];
    const float* Wv    = (const float*)d_in[6];
    float* out = (float*)d_out;

    const int proj_smem = (2*128*PPITCH + 2*32*72) * 4;   // 59392 B
    cudaFuncSetAttribute(proj_kernel,
                         cudaFuncAttributeMaxDynamicSharedMemorySize, proj_smem);

    prep_w<<<dim3(Cc*HSd/1024, 3), 256>>>(Wq, Wk, Wv);
    proj_kernel<<<dim3(Mrows/128, 3), 128, proj_smem>>>(q_vec, k_vec, v_vec);
    attn_kernel<<<640, 128>>>(mask, out);
    combine_kernel<<<dim3(24, 8), 256>>>(out);
}